// round 15
// baseline (speedup 1.0000x reference)
#include <cuda_runtime.h>
#include <cstdint>
#include <math.h>

#define HH   256
#define LL   5
#define TT   1000
#define BB   128

typedef unsigned long long ull;
typedef unsigned int u32;

// Layer-4 outputs for the MLP head.
__device__ float g_hseq[BB][TT];           // 512 KB

__device__ __forceinline__ float tanhapx(float x) {
    float r;
    asm("tanh.approx.f32 %0, %1;" : "=f"(r) : "f"(x));
    return r;
}

// Degree-5 odd polynomial tanh for small arguments (sigmoid gates only).
// Gate args are bounded by ~0.25 (weights U(+-1/16), |x|<=4.5, h small);
// clamped at +-0.5. Max err ~3e-5 at the clamp, ~1e-6 typical. Runs on the
// FMA pipe to offload MUFU (the hypothesized rt-16 bottleneck).
__device__ __forceinline__ float tanhpoly(float x) {
    const float C3 = -0.333333333f;
    const float C5 = 0.1286f;
    x = fminf(fmaxf(x, -0.5f), 0.5f);
    float x2 = x * x;
    float p  = fmaf(C5, x2, C3);
    return fmaf(x * x2, p, x);
}

__device__ __forceinline__ int redux_s32(int v) {
    int r;
    asm volatile("redux.sync.add.s32 %0, %1, 0xffffffff;" : "=r"(r) : "r"(v));
    return r;
}

__device__ __forceinline__ u32 smem_u32(const void* p) {
    u32 a;
    asm("{ .reg .u64 t; cvta.to.shared.u64 t, %1; cvt.u32.u64 %0, t; }"
        : "=r"(a) : "l"(p));
    return a;
}

// ---------------------------------------------------------------- LSTM pipeline
// grid = LL*BB blocks of 128 threads, clustered 5 CTAs per batch element:
// cluster rank = layer l, blockIdx.x / 5 = batch b.
//
// DSMEM handoff + magic fixed point (both validated). ONE change vs the
// 334.0us round: the 6 sigmoid-gate tanhs use tanhpoly (FMA pipe) instead of
// tanh.approx (MUFU). The 4 wide-range tanhs (g-gate, tanh(c)) stay on MUFU.
__global__ void __launch_bounds__(128) __cluster_dims__(LL, 1, 1)
lstm_layer_kernel(const float* __restrict__ x,
                  const float* __restrict__ Wih,
                  const float* __restrict__ Whh,
                  const float* __restrict__ bih,
                  const float* __restrict__ bhh,
                  const float* __restrict__ Whr)
{
    __shared__ __align__(16) ull   inbox[TT];    // 8 KB, written by layer l-1
    __shared__ __align__(16) float xbuf[TT];     // 4 KB, used by layer 0 only
    __shared__ __align__(16) int   part[2][4];   // [t&1][warp]

    const int tid  = threadIdx.x;
    u32 rank;
    asm("mov.u32 %0, %%cluster_ctarank;" : "=r"(rank));
    const int l    = (int)rank;            // layer
    const int b    = blockIdx.x / LL;      // batch element
    const int w    = tid >> 5;             // warp in block (0..3)
    const int lane = tid & 31;

    const float MAGIC  = 12582912.0f;          // 1.5 * 2^23
    const int   MBITS  = 0x4B400000;           // bit pattern of MAGIC
    const float SCALE  = 1048576.0f;           // 2^20
    const float INVSCL = 9.5367431640625e-7f;  // 2^-20

    // ---- per-thread weights: 2 channels x 4 gates ----
    // gate order i,f,g,o; sigmoid(x)=0.5*tanh(0.5x)+0.5 with 0.5 folded in.
    // wH pre-scaled by 2^-20, bias shifted by -MAGIC*wH' (magic fixed point).
    float wI[2][4], wH[2][4], bS[2][4], wR[2];
#pragma unroll
    for (int ch = 0; ch < 2; ++ch) {
        int h = tid + ch * 128;
#pragma unroll
        for (int g = 0; g < 4; ++g) {
            int idx = l * 1024 + g * 256 + h;
            float s = (g == 2) ? 1.0f : 0.5f;
            float wh = Whh[idx] * s * INVSCL;
            wI[ch][g] = Wih[idx] * s;
            wH[ch][g] = wh;
            bS[ch][g] = (bih[idx] + bhh[idx]) * s - MAGIC * wh;
        }
        wR[ch] = Whr[l * 256 + h];
    }

    // ---- init: zero my inbox tags; layer 0 stages x ----
    for (int k = tid; k < TT; k += 128)
        inbox[k] = 0ull;
    if (l == 0) {
        for (int k = tid; k < TT; k += 128)
            xbuf[k] = x[b * TT + k];
    }
    __syncthreads();

    // Cluster barrier: all inboxes zeroed before any producer may store.
    asm volatile("barrier.cluster.arrive.aligned;" ::: "memory");
    asm volatile("barrier.cluster.wait.aligned;"   ::: "memory");

    // Map my inbox base address into the NEXT rank's smem window (producer side).
    const u32 my_inbox = smem_u32(inbox);
    u32 peer_inbox = 0;
    if (l < LL - 1) {
        asm("mapa.shared::cluster.u32 %0, %1, %2;"
            : "=r"(peer_inbox) : "r"(my_inbox), "r"(l + 1));
    }

    float c0 = 0.0f, c1 = 0.0f;
    float hp_raw = MAGIC;                  // fixed-point s=0 at t=0
    float xin = (l == 0) ? xbuf[0] : 0.0f;

    for (int t = 0; t < TT; ++t) {
        // ---- obtain input ----
        float in;
        if (l == 0) {
            in = xin;
            if (t + 1 < TT) xin = xbuf[t + 1];
        } else {
            const u32 slot = my_inbox + (u32)(t * 8);
            const unsigned want = (unsigned)(t + 1);
            ull v;
            asm volatile("ld.volatile.shared.b64 %0, [%1];" : "=l"(v) : "r"(slot));
            while ((unsigned)(v >> 32) != want) {
                asm volatile("ld.volatile.shared.b64 %0, [%1];" : "=l"(v) : "r"(slot));
            }
            in = __uint_as_float((unsigned)v);
        }

        // ---- two channels of the LSTM cell (f32, hp in magic-raw form) ----
        float acc;
        {   // channel 0
            float gi = fmaf(hp_raw, wH[0][0], fmaf(in, wI[0][0], bS[0][0]));
            float gf = fmaf(hp_raw, wH[0][1], fmaf(in, wI[0][1], bS[0][1]));
            float gg = fmaf(hp_raw, wH[0][2], fmaf(in, wI[0][2], bS[0][2]));
            float go = fmaf(hp_raw, wH[0][3], fmaf(in, wI[0][3], bS[0][3]));
            float i_ = fmaf(tanhpoly(gi), 0.5f, 0.5f);
            float f_ = fmaf(tanhpoly(gf), 0.5f, 0.5f);
            float g_ = tanhapx(gg);
            float o_ = fmaf(tanhpoly(go), 0.5f, 0.5f);
            c0 = fmaf(f_, c0, i_ * g_);
            acc = (o_ * tanhapx(c0)) * wR[0];
        }
        {   // channel 1
            float gi = fmaf(hp_raw, wH[1][0], fmaf(in, wI[1][0], bS[1][0]));
            float gf = fmaf(hp_raw, wH[1][1], fmaf(in, wI[1][1], bS[1][1]));
            float gg = fmaf(hp_raw, wH[1][2], fmaf(in, wI[1][2], bS[1][2]));
            float go = fmaf(hp_raw, wH[1][3], fmaf(in, wI[1][3], bS[1][3]));
            float i_ = fmaf(tanhpoly(gi), 0.5f, 0.5f);
            float f_ = fmaf(tanhpoly(gf), 0.5f, 0.5f);
            float g_ = tanhapx(gg);
            float o_ = fmaf(tanhpoly(go), 0.5f, 0.5f);
            c1 = fmaf(f_, c1, i_ * g_);
            acc = fmaf(o_ * tanhapx(c1), wR[1], acc);
        }

        // ---- fixed-point (magic, no F2I) + warp redux + 4-warp combine ----
        int q = __float_as_int(fmaf(acc, SCALE, MAGIC)) - MBITS;
        int r = redux_s32(q);
        if (lane == 0) part[t & 1][w] = r;
        __syncthreads();
        const int* p4 = part[t & 1];
        int s = (p4[0] + p4[1]) + (p4[2] + p4[3]);
        hp_raw = __int_as_float(s + MBITS);        // = MAGIC + (float)s, no I2F

        // ---- publish: one remote 8B store into the next layer's inbox ----
        if (tid == 0) {
            float hval = (hp_raw - MAGIC) * INVSCL;
            if (l < LL - 1) {
                ull v = ((ull)(unsigned)(t + 1) << 32) |
                        (ull)__float_as_uint(hval);
                asm volatile("st.relaxed.cluster.shared::cluster.b64 [%0], %1;"
                             :: "r"(peer_inbox + (u32)(t * 8)), "l"(v)
                             : "memory");
            } else {
                g_hseq[b][t] = hval;
            }
        }
    }

    // Keep all CTAs of the cluster resident until every handoff has landed.
    asm volatile("barrier.cluster.arrive.aligned;" ::: "memory");
    asm volatile("barrier.cluster.wait.aligned;"   ::: "memory");
}

// ---------------------------------------------------------------- MLP head
// 1024 threads/block. Layer 1 (100 x 1000) uses 10 threads per output row
// (100 elements = 25 float4 loads each); partials combine through smem.
__global__ void __launch_bounds__(1024)
mlp_kernel(const float* __restrict__ W1, const float* __restrict__ b1,
           const float* __restrict__ W2, const float* __restrict__ b2,
           const float* __restrict__ W3, const float* __restrict__ b3,
           const float* __restrict__ W4, const float* __restrict__ b4,
           float* __restrict__ out)
{
    __shared__ __align__(16) float hbuf[TT];
    __shared__ float psum[100][10];
    __shared__ float a1[100], a2[100], a3[100];

    const int tid = threadIdx.x;
    const int b   = blockIdx.x;

    for (int k = tid; k < TT; k += 1024)
        hbuf[k] = g_hseq[b][k];
    __syncthreads();

    // ---- layer 1: 1000 -> 100, sigmoid; 10-way split per row ----
    if (tid < 1000) {
        const int row  = tid / 10;
        const int part = tid - row * 10;
        const float* wrow = W1 + row * 1000 + part * 100;
        const float* hrow = hbuf + part * 100;
        float s0 = 0.f, s1 = 0.f, s2 = 0.f, s3 = 0.f;
#pragma unroll
        for (int k = 0; k < 100; k += 4) {
            float4 wv = *(const float4*)(wrow + k);
            float4 hv = *(const float4*)(hrow + k);
            s0 = fmaf(wv.x, hv.x, s0);
            s1 = fmaf(wv.y, hv.y, s1);
            s2 = fmaf(wv.z, hv.z, s2);
            s3 = fmaf(wv.w, hv.w, s3);
        }
        psum[row][part] = (s0 + s1) + (s2 + s3);
    }
    __syncthreads();

    if (tid < 100) {
        float acc = b1[tid];
#pragma unroll
        for (int p = 0; p < 10; ++p)
            acc += psum[tid][p];
        a1[tid] = 1.0f / (1.0f + expf(-acc));
    }
    __syncthreads();

    // ---- layer 2: 100 -> 100, sigmoid ----
    if (tid < 100) {
        const float* wrow = W2 + tid * 100;
        float acc = b2[tid];
#pragma unroll 4
        for (int k = 0; k < 100; ++k)
            acc = fmaf(wrow[k], a1[k], acc);
        a2[tid] = 1.0f / (1.0f + expf(-acc));
    }
    __syncthreads();

    // ---- layer 3: 100 -> 100, relu ----
    if (tid < 100) {
        const float* wrow = W3 + tid * 100;
        float acc = b3[tid];
#pragma unroll 4
        for (int k = 0; k < 100; ++k)
            acc = fmaf(wrow[k], a2[k], acc);
        a3[tid] = fmaxf(acc, 0.0f);
    }
    __syncthreads();

    // ---- layer 4: 100 -> 1 ----
    if (tid == 0) {
        float acc = b4[0];
#pragma unroll 4
        for (int k = 0; k < 100; ++k)
            acc = fmaf(W4[k], a3[k], acc);
        out[b] = acc;
    }
}

extern "C" void kernel_launch(void* const* d_in, const int* in_sizes, int n_in,
                              void* d_out, int out_size)
{
    const float* x   = (const float*)d_in[0];
    const float* Wih = (const float*)d_in[1];
    const float* Whh = (const float*)d_in[2];
    const float* bih = (const float*)d_in[3];
    const float* bhh = (const float*)d_in[4];
    const float* Whr = (const float*)d_in[5];
    const float* W1  = (const float*)d_in[6];
    const float* b1  = (const float*)d_in[7];
    const float* W2  = (const float*)d_in[8];
    const float* b2  = (const float*)d_in[9];
    const float* W3  = (const float*)d_in[10];
    const float* b3  = (const float*)d_in[11];
    const float* W4  = (const float*)d_in[12];
    const float* b4  = (const float*)d_in[13];
    float* out = (float*)d_out;

    lstm_layer_kernel<<<LL * BB, 128>>>(x, Wih, Whh, bih, bhh, Whr);
    mlp_kernel<<<BB, 1024>>>(W1, b1, W2, b2, W3, b3, W4, b4, out);
}

// round 16
// speedup vs baseline: 1.0393x; 1.0393x over previous
#include <cuda_runtime.h>
#include <cstdint>
#include <math.h>

#define HH   256
#define LL   5
#define TT   1000
#define BB   128
#define NT   256    // threads per layer-CTA: 1 hidden channel per thread

typedef unsigned long long ull;
typedef unsigned int u32;

// Layer-4 outputs for the MLP head.
__device__ float g_hseq[BB][TT];           // 512 KB

__device__ __forceinline__ float tanhapx(float x) {
    float r;
    asm("tanh.approx.f32 %0, %1;" : "=f"(r) : "f"(x));
    return r;
}

__device__ __forceinline__ int redux_s32(int v) {
    int r;
    asm volatile("redux.sync.add.s32 %0, %1, 0xffffffff;" : "=r"(r) : "r"(v));
    return r;
}

__device__ __forceinline__ u32 smem_u32(const void* p) {
    u32 a;
    asm("{ .reg .u64 t; cvta.to.shared.u64 t, %1; cvt.u32.u64 %0, t; }"
        : "=r"(a) : "l"(p));
    return a;
}

// ---------------------------------------------------------------- LSTM pipeline
// grid = LL*BB blocks of 256 threads, clustered 5 CTAs per batch element:
// cluster rank = layer l, blockIdx.x / 5 = batch b.
//
// DSMEM handoff + magic fixed point (both validated at 334us). ONE change vs
// that round: 256 threads/block with ONE hidden channel per thread (was 128
// threads x 2 channels). Halves each warp's serial tanh/FMA chain and doubles
// warps/SMSP (4.3 -> 8.6) to fill latency stalls; total work unchanged.
__global__ void __launch_bounds__(NT) __cluster_dims__(LL, 1, 1)
lstm_layer_kernel(const float* __restrict__ x,
                  const float* __restrict__ Wih,
                  const float* __restrict__ Whh,
                  const float* __restrict__ bih,
                  const float* __restrict__ bhh,
                  const float* __restrict__ Whr)
{
    __shared__ __align__(16) ull   inbox[TT];    // 8 KB, written by layer l-1
    __shared__ __align__(16) float xbuf[TT];     // 4 KB, used by layer 0 only
    __shared__ __align__(16) int   part[2][8];   // [t&1][warp]

    const int tid  = threadIdx.x;
    u32 rank;
    asm("mov.u32 %0, %%cluster_ctarank;" : "=r"(rank));
    const int l    = (int)rank;            // layer
    const int b    = blockIdx.x / LL;      // batch element
    const int w    = tid >> 5;             // warp in block (0..7)
    const int lane = tid & 31;

    const float MAGIC  = 12582912.0f;          // 1.5 * 2^23
    const int   MBITS  = 0x4B400000;           // bit pattern of MAGIC
    const float SCALE  = 1048576.0f;           // 2^20
    const float INVSCL = 9.5367431640625e-7f;  // 2^-20

    // ---- per-thread weights: 1 channel x 4 gates ----
    // gate order i,f,g,o; sigmoid(x)=0.5*tanh(0.5x)+0.5 with 0.5 folded in.
    // wH pre-scaled by 2^-20, bias shifted by -MAGIC*wH' (magic fixed point).
    float wI[4], wH[4], bS[4], wR;
#pragma unroll
    for (int g = 0; g < 4; ++g) {
        int idx = l * 1024 + g * 256 + tid;
        float s = (g == 2) ? 1.0f : 0.5f;
        float wh = Whh[idx] * s * INVSCL;
        wI[g] = Wih[idx] * s;
        wH[g] = wh;
        bS[g] = (bih[idx] + bhh[idx]) * s - MAGIC * wh;
    }
    wR = Whr[l * 256 + tid];

    // ---- init: zero my inbox tags; layer 0 stages x ----
    for (int k = tid; k < TT; k += NT)
        inbox[k] = 0ull;
    if (l == 0) {
        for (int k = tid; k < TT; k += NT)
            xbuf[k] = x[b * TT + k];
    }
    __syncthreads();

    // Cluster barrier: all inboxes zeroed before any producer may store.
    asm volatile("barrier.cluster.arrive.aligned;" ::: "memory");
    asm volatile("barrier.cluster.wait.aligned;"   ::: "memory");

    // Map my inbox base address into the NEXT rank's smem window (producer side).
    const u32 my_inbox = smem_u32(inbox);
    u32 peer_inbox = 0;
    if (l < LL - 1) {
        asm("mapa.shared::cluster.u32 %0, %1, %2;"
            : "=r"(peer_inbox) : "r"(my_inbox), "r"(l + 1));
    }

    float c = 0.0f;
    float hp_raw = MAGIC;                  // fixed-point s=0 at t=0
    float xin = (l == 0) ? xbuf[0] : 0.0f;

    for (int t = 0; t < TT; ++t) {
        // ---- obtain input ----
        float in;
        if (l == 0) {
            in = xin;
            if (t + 1 < TT) xin = xbuf[t + 1];
        } else {
            const u32 slot = my_inbox + (u32)(t * 8);
            const unsigned want = (unsigned)(t + 1);
            ull v;
            asm volatile("ld.volatile.shared.b64 %0, [%1];" : "=l"(v) : "r"(slot));
            while ((unsigned)(v >> 32) != want) {
                asm volatile("ld.volatile.shared.b64 %0, [%1];" : "=l"(v) : "r"(slot));
            }
            in = __uint_as_float((unsigned)v);
        }

        // ---- one channel of the LSTM cell (f32, hp in magic-raw form) ----
        float gi = fmaf(hp_raw, wH[0], fmaf(in, wI[0], bS[0]));
        float gf = fmaf(hp_raw, wH[1], fmaf(in, wI[1], bS[1]));
        float gg = fmaf(hp_raw, wH[2], fmaf(in, wI[2], bS[2]));
        float go = fmaf(hp_raw, wH[3], fmaf(in, wI[3], bS[3]));
        float i_ = fmaf(tanhapx(gi), 0.5f, 0.5f);
        float f_ = fmaf(tanhapx(gf), 0.5f, 0.5f);
        float g_ = tanhapx(gg);
        float o_ = fmaf(tanhapx(go), 0.5f, 0.5f);
        c = fmaf(f_, c, i_ * g_);
        float acc = (o_ * tanhapx(c)) * wR;

        // ---- fixed-point (magic, no F2I) + warp redux + 8-warp combine ----
        int q = __float_as_int(fmaf(acc, SCALE, MAGIC)) - MBITS;
        int r = redux_s32(q);
        if (lane == 0) part[t & 1][w] = r;
        __syncthreads();
        const int4 pa = *(const int4*)&part[t & 1][0];
        const int4 pb = *(const int4*)&part[t & 1][4];
        int s = ((pa.x + pa.y) + (pa.z + pa.w))
              + ((pb.x + pb.y) + (pb.z + pb.w));
        hp_raw = __int_as_float(s + MBITS);        // = MAGIC + (float)s, no I2F

        // ---- publish: one remote 8B store into the next layer's inbox ----
        if (tid == 0) {
            float hval = (hp_raw - MAGIC) * INVSCL;
            if (l < LL - 1) {
                ull v = ((ull)(unsigned)(t + 1) << 32) |
                        (ull)__float_as_uint(hval);
                asm volatile("st.relaxed.cluster.shared::cluster.b64 [%0], %1;"
                             :: "r"(peer_inbox + (u32)(t * 8)), "l"(v)
                             : "memory");
            } else {
                g_hseq[b][t] = hval;
            }
        }
    }

    // Keep all CTAs of the cluster resident until every handoff has landed.
    asm volatile("barrier.cluster.arrive.aligned;" ::: "memory");
    asm volatile("barrier.cluster.wait.aligned;"   ::: "memory");
}

// ---------------------------------------------------------------- MLP head
// 1024 threads/block. Layer 1 (100 x 1000) uses 10 threads per output row
// (100 elements = 25 float4 loads each); partials combine through smem.
__global__ void __launch_bounds__(1024)
mlp_kernel(const float* __restrict__ W1, const float* __restrict__ b1,
           const float* __restrict__ W2, const float* __restrict__ b2,
           const float* __restrict__ W3, const float* __restrict__ b3,
           const float* __restrict__ W4, const float* __restrict__ b4,
           float* __restrict__ out)
{
    __shared__ __align__(16) float hbuf[TT];
    __shared__ float psum[100][10];
    __shared__ float a1[100], a2[100], a3[100];

    const int tid = threadIdx.x;
    const int b   = blockIdx.x;

    for (int k = tid; k < TT; k += 1024)
        hbuf[k] = g_hseq[b][k];
    __syncthreads();

    // ---- layer 1: 1000 -> 100, sigmoid; 10-way split per row ----
    if (tid < 1000) {
        const int row  = tid / 10;
        const int part = tid - row * 10;
        const float* wrow = W1 + row * 1000 + part * 100;
        const float* hrow = hbuf + part * 100;
        float s0 = 0.f, s1 = 0.f, s2 = 0.f, s3 = 0.f;
#pragma unroll
        for (int k = 0; k < 100; k += 4) {
            float4 wv = *(const float4*)(wrow + k);
            float4 hv = *(const float4*)(hrow + k);
            s0 = fmaf(wv.x, hv.x, s0);
            s1 = fmaf(wv.y, hv.y, s1);
            s2 = fmaf(wv.z, hv.z, s2);
            s3 = fmaf(wv.w, hv.w, s3);
        }
        psum[row][part] = (s0 + s1) + (s2 + s3);
    }
    __syncthreads();

    if (tid < 100) {
        float acc = b1[tid];
#pragma unroll
        for (int p = 0; p < 10; ++p)
            acc += psum[tid][p];
        a1[tid] = 1.0f / (1.0f + expf(-acc));
    }
    __syncthreads();

    // ---- layer 2: 100 -> 100, sigmoid ----
    if (tid < 100) {
        const float* wrow = W2 + tid * 100;
        float acc = b2[tid];
#pragma unroll 4
        for (int k = 0; k < 100; ++k)
            acc = fmaf(wrow[k], a1[k], acc);
        a2[tid] = 1.0f / (1.0f + expf(-acc));
    }
    __syncthreads();

    // ---- layer 3: 100 -> 100, relu ----
    if (tid < 100) {
        const float* wrow = W3 + tid * 100;
        float acc = b3[tid];
#pragma unroll 4
        for (int k = 0; k < 100; ++k)
            acc = fmaf(wrow[k], a2[k], acc);
        a3[tid] = fmaxf(acc, 0.0f);
    }
    __syncthreads();

    // ---- layer 4: 100 -> 1 ----
    if (tid == 0) {
        float acc = b4[0];
#pragma unroll 4
        for (int k = 0; k < 100; ++k)
            acc = fmaf(W4[k], a3[k], acc);
        out[b] = acc;
    }
}

extern "C" void kernel_launch(void* const* d_in, const int* in_sizes, int n_in,
                              void* d_out, int out_size)
{
    const float* x   = (const float*)d_in[0];
    const float* Wih = (const float*)d_in[1];
    const float* Whh = (const float*)d_in[2];
    const float* bih = (const float*)d_in[3];
    const float* bhh = (const float*)d_in[4];
    const float* Whr = (const float*)d_in[5];
    const float* W1  = (const float*)d_in[6];
    const float* b1  = (const float*)d_in[7];
    const float* W2  = (const float*)d_in[8];
    const float* b2  = (const float*)d_in[9];
    const float* W3  = (const float*)d_in[10];
    const float* b3  = (const float*)d_in[11];
    const float* W4  = (const float*)d_in[12];
    const float* b4  = (const float*)d_in[13];
    float* out = (float*)d_out;

    lstm_layer_kernel<<<LL * BB, NT>>>(x, Wih, Whh, bih, bhh, Whr);
    mlp_kernel<<<BB, 1024>>>(W1, b1, W2, b2, W3, b3, W4, b4, out);
}

// round 17
// speedup vs baseline: 1.2675x; 1.2195x over previous
#include <cuda_runtime.h>
#include <cstdint>
#include <math.h>

#define HH   256
#define LL   5
#define TT   1000
#define BB   128

typedef unsigned long long ull;
typedef unsigned int u32;

// Layer-4 outputs for the MLP head.
__device__ float g_hseq[BB][TT];           // 512 KB

__device__ __forceinline__ float tanhapx(float x) {
    float r;
    asm("tanh.approx.f32 %0, %1;" : "=f"(r) : "f"(x));
    return r;
}

__device__ __forceinline__ int redux_s32(int v) {
    int r;
    asm volatile("redux.sync.add.s32 %0, %1, 0xffffffff;" : "=r"(r) : "r"(v));
    return r;
}

__device__ __forceinline__ u32 smem_u32(const void* p) {
    u32 a;
    asm("{ .reg .u64 t; cvta.to.shared.u64 t, %1; cvt.u32.u64 %0, t; }"
        : "=r"(a) : "l"(p));
    return a;
}

__device__ __forceinline__ ull lds_vol64(u32 addr) {
    ull v;
    asm volatile("ld.volatile.shared.b64 %0, [%1];" : "=l"(v) : "r"(addr));
    return v;
}

// ---------------------------------------------------------------- LSTM pipeline
// grid = LL*BB blocks of 128 threads, clustered 5 CTAs per batch element:
// cluster rank = layer l, blockIdx.x / 5 = batch b.
//
// DSMEM handoff + magic fixed point (both validated at 334us, 128thr x 2ch).
// ONE change vs the 334us round: the inbox slot for step t+1 is PREFETCHED
// into a register during step t's compute (check-at-consume). The poll LDS
// (29+cyc) moves off the recurrence-critical path; a stale prefetch is caught
// by the tag check and re-polled.
__global__ void __launch_bounds__(128) __cluster_dims__(LL, 1, 1)
lstm_layer_kernel(const float* __restrict__ x,
                  const float* __restrict__ Wih,
                  const float* __restrict__ Whh,
                  const float* __restrict__ bih,
                  const float* __restrict__ bhh,
                  const float* __restrict__ Whr)
{
    __shared__ __align__(16) ull   inbox[TT];    // 8 KB, written by layer l-1
    __shared__ __align__(16) float xbuf[TT];     // 4 KB, used by layer 0 only
    __shared__ __align__(16) int   part[2][4];   // [t&1][warp]

    const int tid  = threadIdx.x;
    u32 rank;
    asm("mov.u32 %0, %%cluster_ctarank;" : "=r"(rank));
    const int l    = (int)rank;            // layer
    const int b    = blockIdx.x / LL;      // batch element
    const int w    = tid >> 5;             // warp in block (0..3)
    const int lane = tid & 31;

    const float MAGIC  = 12582912.0f;          // 1.5 * 2^23
    const int   MBITS  = 0x4B400000;           // bit pattern of MAGIC
    const float SCALE  = 1048576.0f;           // 2^20
    const float INVSCL = 9.5367431640625e-7f;  // 2^-20

    // ---- per-thread weights: 2 channels x 4 gates ----
    // gate order i,f,g,o; sigmoid(x)=0.5*tanh(0.5x)+0.5 with 0.5 folded in.
    // wH pre-scaled by 2^-20, bias shifted by -MAGIC*wH' (magic fixed point).
    float wI[2][4], wH[2][4], bS[2][4], wR[2];
#pragma unroll
    for (int ch = 0; ch < 2; ++ch) {
        int h = tid + ch * 128;
#pragma unroll
        for (int g = 0; g < 4; ++g) {
            int idx = l * 1024 + g * 256 + h;
            float s = (g == 2) ? 1.0f : 0.5f;
            float wh = Whh[idx] * s * INVSCL;
            wI[ch][g] = Wih[idx] * s;
            wH[ch][g] = wh;
            bS[ch][g] = (bih[idx] + bhh[idx]) * s - MAGIC * wh;
        }
        wR[ch] = Whr[l * 256 + h];
    }

    // ---- init: zero my inbox tags; layer 0 stages x ----
    for (int k = tid; k < TT; k += 128)
        inbox[k] = 0ull;
    if (l == 0) {
        for (int k = tid; k < TT; k += 128)
            xbuf[k] = x[b * TT + k];
    }
    __syncthreads();

    // Cluster barrier: all inboxes zeroed before any producer may store.
    asm volatile("barrier.cluster.arrive.aligned;" ::: "memory");
    asm volatile("barrier.cluster.wait.aligned;"   ::: "memory");

    // Map my inbox base address into the NEXT rank's smem window (producer side).
    const u32 my_inbox = smem_u32(inbox);
    u32 peer_inbox = 0;
    if (l < LL - 1) {
        asm("mapa.shared::cluster.u32 %0, %1, %2;"
            : "=r"(peer_inbox) : "r"(my_inbox), "r"(l + 1));
    }

    float c0 = 0.0f, c1 = 0.0f;
    float hp_raw = MAGIC;                  // fixed-point s=0 at t=0
    float xin = 0.0f;
    ull   pre = 0ull;                      // prefetched inbox word for step t
    if (l == 0) xin = xbuf[0];
    else        pre = lds_vol64(my_inbox); // slot 0

    for (int t = 0; t < TT; ++t) {
        // ---- consume input: validate prefetched tag, re-poll only if stale ----
        float in;
        if (l == 0) {
            in = xin;
            if (t + 1 < TT) xin = xbuf[t + 1];
        } else {
            const u32 slot = my_inbox + (u32)(t * 8);
            const unsigned want = (unsigned)(t + 1);
            ull v = pre;
            while ((unsigned)(v >> 32) != want)
                v = lds_vol64(slot);
            in = __uint_as_float((unsigned)v);
            if (t + 1 < TT)
                pre = lds_vol64(slot + 8);   // prefetch next slot, hidden under compute
        }

        // ---- two channels of the LSTM cell (f32, hp in magic-raw form) ----
        float acc;
        {   // channel 0
            float gi = fmaf(hp_raw, wH[0][0], fmaf(in, wI[0][0], bS[0][0]));
            float gf = fmaf(hp_raw, wH[0][1], fmaf(in, wI[0][1], bS[0][1]));
            float gg = fmaf(hp_raw, wH[0][2], fmaf(in, wI[0][2], bS[0][2]));
            float go = fmaf(hp_raw, wH[0][3], fmaf(in, wI[0][3], bS[0][3]));
            float i_ = fmaf(tanhapx(gi), 0.5f, 0.5f);
            float f_ = fmaf(tanhapx(gf), 0.5f, 0.5f);
            float g_ = tanhapx(gg);
            float o_ = fmaf(tanhapx(go), 0.5f, 0.5f);
            c0 = fmaf(f_, c0, i_ * g_);
            acc = (o_ * tanhapx(c0)) * wR[0];
        }
        {   // channel 1
            float gi = fmaf(hp_raw, wH[1][0], fmaf(in, wI[1][0], bS[1][0]));
            float gf = fmaf(hp_raw, wH[1][1], fmaf(in, wI[1][1], bS[1][1]));
            float gg = fmaf(hp_raw, wH[1][2], fmaf(in, wI[1][2], bS[1][2]));
            float go = fmaf(hp_raw, wH[1][3], fmaf(in, wI[1][3], bS[1][3]));
            float i_ = fmaf(tanhapx(gi), 0.5f, 0.5f);
            float f_ = fmaf(tanhapx(gf), 0.5f, 0.5f);
            float g_ = tanhapx(gg);
            float o_ = fmaf(tanhapx(go), 0.5f, 0.5f);
            c1 = fmaf(f_, c1, i_ * g_);
            acc = fmaf(o_ * tanhapx(c1), wR[1], acc);
        }

        // ---- fixed-point (magic, no F2I) + warp redux + 4-warp combine ----
        int q = __float_as_int(fmaf(acc, SCALE, MAGIC)) - MBITS;
        int r = redux_s32(q);
        if (lane == 0) part[t & 1][w] = r;
        __syncthreads();
        const int* p4 = part[t & 1];
        int s = (p4[0] + p4[1]) + (p4[2] + p4[3]);
        hp_raw = __int_as_float(s + MBITS);        // = MAGIC + (float)s, no I2F

        // ---- publish: one remote 8B store into the next layer's inbox ----
        if (tid == 0) {
            float hval = (hp_raw - MAGIC) * INVSCL;
            if (l < LL - 1) {
                ull v = ((ull)(unsigned)(t + 1) << 32) |
                        (ull)__float_as_uint(hval);
                asm volatile("st.relaxed.cluster.shared::cluster.b64 [%0], %1;"
                             :: "r"(peer_inbox + (u32)(t * 8)), "l"(v)
                             : "memory");
            } else {
                g_hseq[b][t] = hval;
            }
        }
    }

    // Keep all CTAs of the cluster resident until every handoff has landed.
    asm volatile("barrier.cluster.arrive.aligned;" ::: "memory");
    asm volatile("barrier.cluster.wait.aligned;"   ::: "memory");
}

// ---------------------------------------------------------------- MLP head
// 1024 threads/block. Layer 1 (100 x 1000) uses 10 threads per output row
// (100 elements = 25 float4 loads each); partials combine through smem.
__global__ void __launch_bounds__(1024)
mlp_kernel(const float* __restrict__ W1, const float* __restrict__ b1,
           const float* __restrict__ W2, const float* __restrict__ b2,
           const float* __restrict__ W3, const float* __restrict__ b3,
           const float* __restrict__ W4, const float* __restrict__ b4,
           float* __restrict__ out)
{
    __shared__ __align__(16) float hbuf[TT];
    __shared__ float psum[100][10];
    __shared__ float a1[100], a2[100], a3[100];

    const int tid = threadIdx.x;
    const int b   = blockIdx.x;

    for (int k = tid; k < TT; k += 1024)
        hbuf[k] = g_hseq[b][k];
    __syncthreads();

    // ---- layer 1: 1000 -> 100, sigmoid; 10-way split per row ----
    if (tid < 1000) {
        const int row  = tid / 10;
        const int part = tid - row * 10;
        const float* wrow = W1 + row * 1000 + part * 100;
        const float* hrow = hbuf + part * 100;
        float s0 = 0.f, s1 = 0.f, s2 = 0.f, s3 = 0.f;
#pragma unroll
        for (int k = 0; k < 100; k += 4) {
            float4 wv = *(const float4*)(wrow + k);
            float4 hv = *(const float4*)(hrow + k);
            s0 = fmaf(wv.x, hv.x, s0);
            s1 = fmaf(wv.y, hv.y, s1);
            s2 = fmaf(wv.z, hv.z, s2);
            s3 = fmaf(wv.w, hv.w, s3);
        }
        psum[row][part] = (s0 + s1) + (s2 + s3);
    }
    __syncthreads();

    if (tid < 100) {
        float acc = b1[tid];
#pragma unroll
        for (int p = 0; p < 10; ++p)
            acc += psum[tid][p];
        a1[tid] = 1.0f / (1.0f + expf(-acc));
    }
    __syncthreads();

    // ---- layer 2: 100 -> 100, sigmoid ----
    if (tid < 100) {
        const float* wrow = W2 + tid * 100;
        float acc = b2[tid];
#pragma unroll 4
        for (int k = 0; k < 100; ++k)
            acc = fmaf(wrow[k], a1[k], acc);
        a2[tid] = 1.0f / (1.0f + expf(-acc));
    }
    __syncthreads();

    // ---- layer 3: 100 -> 100, relu ----
    if (tid < 100) {
        const float* wrow = W3 + tid * 100;
        float acc = b3[tid];
#pragma unroll 4
        for (int k = 0; k < 100; ++k)
            acc = fmaf(wrow[k], a2[k], acc);
        a3[tid] = fmaxf(acc, 0.0f);
    }
    __syncthreads();

    // ---- layer 4: 100 -> 1 ----
    if (tid == 0) {
        float acc = b4[0];
#pragma unroll 4
        for (int k = 0; k < 100; ++k)
            acc = fmaf(W4[k], a3[k], acc);
        out[b] = acc;
    }
}

extern "C" void kernel_launch(void* const* d_in, const int* in_sizes, int n_in,
                              void* d_out, int out_size)
{
    const float* x   = (const float*)d_in[0];
    const float* Wih = (const float*)d_in[1];
    const float* Whh = (const float*)d_in[2];
    const float* bih = (const float*)d_in[3];
    const float* bhh = (const float*)d_in[4];
    const float* Whr = (const float*)d_in[5];
    const float* W1  = (const float*)d_in[6];
    const float* b1  = (const float*)d_in[7];
    const float* W2  = (const float*)d_in[8];
    const float* b2  = (const float*)d_in[9];
    const float* W3  = (const float*)d_in[10];
    const float* b3  = (const float*)d_in[11];
    const float* W4  = (const float*)d_in[12];
    const float* b4  = (const float*)d_in[13];
    float* out = (float*)d_out;

    lstm_layer_kernel<<<LL * BB, 128>>>(x, Wih, Whh, bih, bhh, Whr);
    mlp_kernel<<<BB, 1024>>>(W1, b1, W2, b2, W3, b3, W4, b4, out);
}